// round 16
// baseline (speedup 1.0000x reference)
#include <cuda_runtime.h>
#include <cuda_fp16.h>
#include <cstdint>

// Problem constants
#define N_TOK 16384
#define DIM   1024
#define HID   4096
#define HHALF 2048
#define NEXP  8
#define EPSLN 1e-5f

// CTA tile
#define BM 128
#define BN 256
#define B_ROWB 2080    // B smem row stride bytes (256 u64 + 32B pad): conflict-free LDS.64
#define B_ROWU 260     // same in u64

// ---------------- scratch -------------------------------------------------------
__device__ __half    g_xnh[(size_t)N_TOK * DIM];
__device__ __half    g_xnl[(size_t)N_TOK * DIM];
__device__ float     g_hr [(size_t)N_TOK * HHALF];
__device__ uint32_t  g_hh [(size_t)(2 * N_TOK) * (HID / 2)];
__device__ uint32_t  g_yh [(size_t)(2 * N_TOK) * (DIM / 2)];
__device__ uint64_t  g_w1hp[(size_t)(DIM / 4) * HHALF];
__device__ uint64_t  g_w1lp[(size_t)(DIM / 4) * HHALF];
__device__ uint64_t  g_ew1p[(size_t)NEXP * (DIM / 4) * HID];
__device__ uint64_t  g_ew2p[(size_t)NEXP * (HID / 4) * DIM];
__device__ int   g_cnt[NEXP];
__device__ int   g_off[NEXP];
__device__ int   g_fill[NEXP];
__device__ int   g_e12[N_TOK];
__device__ float g_g1[N_TOK];
__device__ float g_g2[N_TOK];
__device__ int   g_list[2 * N_TOK];
__device__ int   g_s1[N_TOK];
__device__ int   g_s2[N_TOK];

// ---------------- helpers -------------------------------------------------------
__device__ __forceinline__ uint32_t smem_u32(const void* p) {
    uint32_t a;
    asm("{ .reg .u64 t; cvta.to.shared.u64 t, %1; cvt.u32.u64 %0, t; }" : "=r"(a) : "l"(p));
    return a;
}
#define CP16(dst, src) \
    asm volatile("cp.async.cg.shared.global [%0], [%1], 16;" :: "r"(dst), "l"(src) : "memory")
#define CP_COMMIT() asm volatile("cp.async.commit_group;" ::: "memory")
#define CP_WAIT2()  asm volatile("cp.async.wait_group 2;" ::: "memory")
#define CP_WAIT0()  asm volatile("cp.async.wait_group 0;" ::: "memory")

#define LDSM4(r0, r1, r2, r3, addr) \
    asm volatile("ldmatrix.sync.aligned.m8n8.x4.shared.b16 {%0,%1,%2,%3}, [%4];" \
                 : "=r"(r0), "=r"(r1), "=r"(r2), "=r"(r3) : "r"(addr))

__device__ __forceinline__ void mma16(float c[4], const uint32_t a[4], const uint32_t b[2]) {
    asm volatile(
        "mma.sync.aligned.m16n8k16.row.col.f32.f16.f16.f32 "
        "{%0,%1,%2,%3}, {%4,%5,%6,%7}, {%8,%9}, {%0,%1,%2,%3};"
        : "+f"(c[0]), "+f"(c[1]), "+f"(c[2]), "+f"(c[3])
        : "r"(a[0]), "r"(a[1]), "r"(a[2]), "r"(a[3]), "r"(b[0]), "r"(b[1]));
}

// ---------------- LayerNorm: fp16 hi + fp16 lo residual --------------------------
__global__ void ln_kernel(const float* __restrict__ x,
                          const float* __restrict__ gam,
                          const float* __restrict__ bet) {
    int row = blockIdx.x;
    const float* xr = x + (size_t)row * DIM;
    float s = 0.f, ss = 0.f;
    for (int i = threadIdx.x; i < DIM; i += 256) {
        float v = xr[i];
        s += v; ss += v * v;
    }
    __shared__ float sh[64];
    for (int o = 16; o; o >>= 1) {
        s  += __shfl_xor_sync(0xFFFFFFFFu, s,  o);
        ss += __shfl_xor_sync(0xFFFFFFFFu, ss, o);
    }
    int w = threadIdx.x >> 5, l = threadIdx.x & 31;
    if (l == 0) { sh[w] = s; sh[w + 32] = ss; }
    __syncthreads();
    if (w == 0) {
        s  = (l < 8) ? sh[l] : 0.f;
        ss = (l < 8) ? sh[l + 32] : 0.f;
        for (int o = 4; o; o >>= 1) {
            s  += __shfl_xor_sync(0xFFFFFFFFu, s,  o);
            ss += __shfl_xor_sync(0xFFFFFFFFu, ss, o);
        }
        if (l == 0) { sh[0] = s; sh[1] = ss; }
    }
    __syncthreads();
    float mu  = sh[0] * (1.0f / DIM);
    float var = sh[1] * (1.0f / DIM) - mu * mu;
    float r   = rsqrtf(var + EPSLN);
    for (int i = threadIdx.x; i < DIM; i += 256) {
        float v = (xr[i] - mu) * r * gam[i] + bet[i];
        __half h = __float2half_rn(v);
        g_xnh[(size_t)row * DIM + i] = h;
        g_xnl[(size_t)row * DIM + i] = __float2half_rn(v - __half2float(h));
    }
}

// ---------------- weight prep: u64-interleaved fp16 pack -------------------------
__global__ void packw2(const float* __restrict__ in, uint64_t* __restrict__ out,
                       int N) {
    size_t idx = (size_t)blockIdx.x * 256 + threadIdx.x;
    size_t nh = (size_t)N / 2;
    size_t rowp = idx / nh;
    size_t n = (idx % nh) * 2;
    size_t ko = rowp >> 2, lc = rowp & 3;
    size_t k0 = ko * 16 + lc * 2;
    const float* w0 = in + k0 * N + n;
    float a0 = w0[0],         a0b = w0[1];
    float a1 = w0[N],         a1b = w0[N + 1];
    float a8 = w0[8 * N],     a8b = w0[8 * N + 1];
    float a9 = w0[9 * N],     a9b = w0[9 * N + 1];
    __half2 h0 = __floats2half2_rn(a0, a1);
    __half2 h1 = __floats2half2_rn(a8, a9);
    __half2 h2 = __floats2half2_rn(a0b, a1b);
    __half2 h3 = __floats2half2_rn(a8b, a9b);
    uint4 o;
    o.x = *(uint32_t*)&h0; o.y = *(uint32_t*)&h1;
    o.z = *(uint32_t*)&h2; o.w = *(uint32_t*)&h3;
    *(uint4*)(out + rowp * N + n) = o;
}

__global__ void packw2_split(const float* __restrict__ in,
                             uint64_t* __restrict__ hi, uint64_t* __restrict__ lo,
                             int N) {
    size_t idx = (size_t)blockIdx.x * 256 + threadIdx.x;
    size_t nh = (size_t)N / 2;
    size_t rowp = idx / nh;
    size_t n = (idx % nh) * 2;
    size_t ko = rowp >> 2, lc = rowp & 3;
    size_t k0 = ko * 16 + lc * 2;
    const float* w0 = in + k0 * N + n;
    float v[8] = { w0[0], w0[N], w0[8 * N], w0[9 * N],
                   w0[1], w0[N + 1], w0[8 * N + 1], w0[9 * N + 1] };
    __half hh[8];
    __half ll[8];
#pragma unroll
    for (int j = 0; j < 8; j++) {
        hh[j] = __float2half_rn(v[j]);
        ll[j] = __float2half_rn(v[j] - __half2float(hh[j]));
    }
    uint4 oh, ol;
    __half2 t;
    t = __halves2half2(hh[0], hh[1]); oh.x = *(uint32_t*)&t;
    t = __halves2half2(hh[2], hh[3]); oh.y = *(uint32_t*)&t;
    t = __halves2half2(hh[4], hh[5]); oh.z = *(uint32_t*)&t;
    t = __halves2half2(hh[6], hh[7]); oh.w = *(uint32_t*)&t;
    t = __halves2half2(ll[0], ll[1]); ol.x = *(uint32_t*)&t;
    t = __halves2half2(ll[2], ll[3]); ol.y = *(uint32_t*)&t;
    t = __halves2half2(ll[4], ll[5]); ol.z = *(uint32_t*)&t;
    t = __halves2half2(ll[6], ll[7]); ol.w = *(uint32_t*)&t;
    *(uint4*)(hi + rowp * N + n) = oh;
    *(uint4*)(lo + rowp * N + n) = ol;
}

// ---------------- Router logits + softmax top-2 + gates (float4 MLP) -------------
__global__ void router_kernel(const float* __restrict__ w2,
                              const float* __restrict__ b2) {
    int warp = threadIdx.x >> 5, lane = threadIdx.x & 31;
    int t = blockIdx.x * 8 + warp;
    const float4* hrow = (const float4*)(g_hr + (size_t)t * HHALF);
    float acc[NEXP] = {};
#pragma unroll 4
    for (int i = lane; i < HHALF / 4; i += 32) {
        float4 h4 = hrow[i];
        const float4* wp = (const float4*)(w2 + (size_t)i * 4 * NEXP);
        float hv[4] = {h4.x, h4.y, h4.z, h4.w};
#pragma unroll
        for (int j = 0; j < 4; j++) {
            float4 w0 = __ldg(wp + j * 2), w1 = __ldg(wp + j * 2 + 1);
            acc[0] += hv[j] * w0.x; acc[1] += hv[j] * w0.y;
            acc[2] += hv[j] * w0.z; acc[3] += hv[j] * w0.w;
            acc[4] += hv[j] * w1.x; acc[5] += hv[j] * w1.y;
            acc[6] += hv[j] * w1.z; acc[7] += hv[j] * w1.w;
        }
    }
    for (int o = 16; o; o >>= 1)
#pragma unroll
        for (int e = 0; e < NEXP; e++)
            acc[e] += __shfl_xor_sync(0xFFFFFFFFu, acc[e], o);
    if (lane == 0) {
        float l[NEXP];
#pragma unroll
        for (int e = 0; e < NEXP; e++) l[e] = acc[e] + b2[e];
        int e1 = 0;
        for (int e = 1; e < NEXP; e++) if (l[e] > l[e1]) e1 = e;
        int e2 = -1;
        for (int e = 0; e < NEXP; e++) {
            if (e == e1) continue;
            if (e2 < 0 || l[e] > l[e2]) e2 = e;
        }
        float ed  = expf(l[e2] - l[e1]);
        float inv = 1.f / (1.f + ed);
        g_e12[t] = e1 | (e2 << 8);
        g_g1[t] = inv;
        g_g2[t] = ed * inv;
        atomicAdd(&g_cnt[e1], 1);
        atomicAdd(&g_cnt[e2], 1);
    }
}

__global__ void zero_cnt_kernel() {
    if (threadIdx.x < NEXP) g_cnt[threadIdx.x] = 0;
}
__global__ void scan_kernel() {
    if (threadIdx.x == 0) {
        int s = 0;
        for (int e = 0; e < NEXP; e++) { g_off[e] = s; s += g_cnt[e]; g_fill[e] = 0; }
    }
}
__global__ void place_kernel() {
    int t = blockIdx.x * 256 + threadIdx.x;
    if (t >= N_TOK) return;
    int e12 = g_e12[t];
    int e1 = e12 & 0xFF, e2 = e12 >> 8;
    int s1 = g_off[e1] + atomicAdd(&g_fill[e1], 1);
    g_list[s1] = t; g_s1[t] = s1;
    int s2 = g_off[e2] + atomicAdd(&g_fill[e2], 1);
    g_list[s2] = t; g_s2[t] = s2;
}

// ---------------- final combine: out = x + g1*y[s1] + g2*y[s2] (y fp16) ----------
__global__ void combine_kernel(const float* __restrict__ x, float* __restrict__ out) {
    int t = blockIdx.x;
    int s1 = g_s1[t], s2 = g_s2[t];
    float a = g_g1[t], b = g_g2[t];
    int i = threadIdx.x;
    float4 xv = ((const float4*)(x + (size_t)t * DIM))[i];
    uint2 u1 = ((const uint2*)(g_yh + (size_t)s1 * (DIM / 2)))[i];
    uint2 u2 = ((const uint2*)(g_yh + (size_t)s2 * (DIM / 2)))[i];
    float2 p1a = __half22float2(*(__half2*)&u1.x);
    float2 p1b = __half22float2(*(__half2*)&u1.y);
    float2 p2a = __half22float2(*(__half2*)&u2.x);
    float2 p2b = __half22float2(*(__half2*)&u2.y);
    float4 r;
    r.x = xv.x + a * p1a.x + b * p2a.x;
    r.y = xv.y + a * p1a.y + b * p2a.y;
    r.z = xv.z + a * p1b.x + b * p2b.x;
    r.w = xv.w + a * p1b.y + b * p2b.y;
    ((float4*)(out + (size_t)t * DIM))[i] = r;
}

// ---------------- Router GEMM: split-fp16, ldmatrix + LDS.64, 4-stage ------------
__global__ void __launch_bounds__(256, 1)
gemm_router16(const uint64_t* __restrict__ Wh, const uint64_t* __restrict__ Wl,
              const float* __restrict__ bias) {
    constexpr int NC   = DIM / 32;
    constexpr int AST4 = 80;
    constexpr int ASZ  = BM * AST4;
    constexpr int BSZ  = 8 * B_ROWB;
    constexpr int STG  = 2 * ASZ + 2 * BSZ;

    int bm = blockIdx.y * BM, bn = blockIdx.x * BN;
    extern __shared__ char smc[];
    uint32_t smb = smem_u32(smc);
    int tid = threadIdx.x, lane = tid & 31, wid = tid >> 5;
    int wm = (wid >> 2) * 64, wn = (wid & 3) * 64;

    const uint32_t* ah[2];
    const uint32_t* al[2];
    uint32_t adst[2];
#pragma unroll
    for (int j = 0; j < 2; j++) {
        int id = tid + 256 * j;
        int row = id >> 2, c4 = id & 3;
        adst[j] = (uint32_t)row * AST4 + c4 * 16;
        ah[j] = (const uint32_t*)g_xnh + (size_t)(bm + row) * (DIM / 2) + c4 * 4;
        al[j] = (const uint32_t*)g_xnl + (size_t)(bm + row) * (DIM / 2) + c4 * 4;
    }
    const uint64_t* bh[4];
    const uint64_t* bl[4];
    uint32_t bdst[4];
#pragma unroll
    for (int j = 0; j < 4; j++) {
        int id = tid + 256 * j;
        int p = id >> 7, nn = (id & 127) * 2;
        bdst[j] = (uint32_t)p * B_ROWB + nn * 8;
        bh[j] = Wh + (size_t)p * HHALF + bn + nn;
        bl[j] = Wl + (size_t)p * HHALF + bn + nn;
    }

    auto load = [&](int i, int st) {
        uint32_t s0 = smb + (uint32_t)st * STG;
        int ko = i * 16;
        size_t bko = (size_t)i * 8 * HHALF;
#pragma unroll
        for (int j = 0; j < 2; j++) {
            CP16(s0 + adst[j], ah[j] + ko);
            CP16(s0 + ASZ + adst[j], al[j] + ko);
        }
#pragma unroll
        for (int j = 0; j < 4; j++) {
            CP16(s0 + 2 * ASZ + bdst[j], bh[j] + bko);
            CP16(s0 + 2 * ASZ + BSZ + bdst[j], bl[j] + bko);
        }
        CP_COMMIT();
    };

    float c[4][8][4] = {};
    load(0, 0);
    load(1, 1);
    load(2, 2);

    int lr = lane >> 2, lc = lane & 3;
    uint32_t arow_off = (uint32_t)(wm + (lane & 15)) * AST4 + (lane >> 4) * 16;
    for (int i = 0; i < NC; i++) {
        int st = i & 3;
        if (i + 3 < NC) { CP_WAIT2(); } else { CP_WAIT0(); }
        __syncthreads();
        if (i + 3 < NC) load(i + 3, (i + 3) & 3);

        uint32_t sA  = smb + st * STG;
        uint32_t sA2 = sA + ASZ;
        const uint64_t* Bu = (const uint64_t*)(smc + st * STG + 2 * ASZ);
        const uint64_t* Bl2 = (const uint64_t*)(smc + st * STG + 2 * ASZ + BSZ);
#pragma unroll
        for (int ks = 0; ks < 2; ks++) {
            uint32_t a[4][4], a2[4][4], b[8][2], b2[8][2];
#pragma unroll
            for (int mt = 0; mt < 4; mt++) {
                LDSM4(a[mt][0], a[mt][1], a[mt][2], a[mt][3],
                      sA + arow_off + mt * 16 * AST4 + ks * 32);
                LDSM4(a2[mt][0], a2[mt][1], a2[mt][2], a2[mt][3],
                      sA2 + arow_off + mt * 16 * AST4 + ks * 32);
            }
            int prow = ks * 4 + lc;
#pragma unroll
            for (int nt = 0; nt < 8; nt++) {
                uint2 v  = *(const uint2*)(Bu  + (size_t)prow * B_ROWU + wn + nt * 8 + lr);
                uint2 v2 = *(const uint2*)(Bl2 + (size_t)prow * B_ROWU + wn + nt * 8 + lr);
                b[nt][0] = v.x;  b[nt][1] = v.y;
                b2[nt][0] = v2.x; b2[nt][1] = v2.y;
            }
#pragma unroll
            for (int mt = 0; mt < 4; mt++)
#pragma unroll
                for (int nt = 0; nt < 8; nt++) {
                    mma16(c[mt][nt], a[mt],  b[nt]);
                    mma16(c[mt][nt], a[mt],  b2[nt]);
                    mma16(c[mt][nt], a2[mt], b[nt]);
                }
        }
    }

#pragma unroll
    for (int mt = 0; mt < 4; mt++) {
#pragma unroll
        for (int half = 0; half < 2; half++) {
            int r = bm + wm + mt * 16 + lr + half * 8;
            float* row = g_hr + (size_t)r * HHALF;
#pragma unroll
            for (int nt = 0; nt < 8; nt++) {
                int col = bn + wn + nt * 8 + lc * 2;
                float v0 = c[mt][nt][half * 2]     + bias[col];
                float v1 = c[mt][nt][half * 2 + 1] + bias[col + 1];
                float2 st2;
                st2.x = fmaxf(v0, 0.f); st2.y = fmaxf(v1, 0.f);
                *(float2*)(row + col) = st2;
            }
        }
    }
}

// ---------------- Expert GEMMs: fp16, ldmatrix + LDS.64, BKC=64, 4-stage ---------
template <int MODE>
__global__ void __launch_bounds__(256, 1)
moe_mma16(const uint64_t* __restrict__ Wp, const float* __restrict__ bias) {
    constexpr int Kd   = (MODE == 2) ? HID : DIM;
    constexpr int Nd   = (MODE == 1) ? HID : DIM;
    constexpr int NC   = Kd / 64;
    constexpr int AST4 = 144;
    constexpr int ASZ  = BM * AST4;
    constexpr int BSZ  = 16 * B_ROWB;
    constexpr int STG  = ASZ + BSZ;

    int bm = blockIdx.y * BM, bn = blockIdx.x * BN;
    int e = blockIdx.z;
    int cnt = g_cnt[e];
    if (bm >= cnt) return;
    int base = g_off[e];
    const uint64_t* W = Wp + (size_t)e * (Kd / 4) * Nd;
    const float* bp = bias + e * Nd;

    extern __shared__ char smc[];
    uint32_t smb = smem_u32(smc);
    int tid = threadIdx.x, lane = tid & 31, wid = tid >> 5;
    int wm = (wid >> 2) * 64, wn = (wid & 3) * 64;

    const uint32_t* ah[4];
    uint32_t adst[4];
#pragma unroll
    for (int j = 0; j < 4; j++) {
        int id = tid + 256 * j;
        int row = id >> 3, c4 = id & 7;
        adst[j] = (uint32_t)row * AST4 + c4 * 16;
        int r = bm + row; if (r >= cnt) r = cnt - 1;
        if (MODE == 1) {
            int tok = g_list[base + r];
            ah[j] = (const uint32_t*)g_xnh + (size_t)tok * (DIM / 2) + c4 * 4;
        } else {
            ah[j] = g_hh + (size_t)(base + r) * (HID / 2) + c4 * 4;
        }
    }
    const uint64_t* bh[8];
    uint32_t bdst[8];
#pragma unroll
    for (int j = 0; j < 8; j++) {
        int id = tid + 256 * j;
        int p = id >> 7, nn = (id & 127) * 2;
        bdst[j] = (uint32_t)p * B_ROWB + nn * 8;
        bh[j] = W + (size_t)p * Nd + bn + nn;
    }

    auto load = [&](int i, int st) {
        uint32_t s0 = smb + (uint32_t)st * STG;
        int ko = i * 32;
        size_t bko = (size_t)i * 16 * Nd;
#pragma unroll
        for (int j = 0; j < 4; j++) CP16(s0 + adst[j], ah[j] + ko);
#pragma unroll
        for (int j = 0; j < 8; j++) CP16(s0 + ASZ + bdst[j], bh[j] + bko);
        CP_COMMIT();
    };

    float c[4][8][4] = {};
    load(0, 0);
    load(1, 1);
    load(2, 2);

    int lr = lane >> 2, lc = lane & 3;
    uint32_t arow_off = (uint32_t)(wm + (lane & 15)) * AST4 + (lane >> 4) * 16;
    for (int i = 0; i < NC; i++) {
        int st = i & 3;
        if (i + 3 < NC) { CP_WAIT2(); } else { CP_WAIT0(); }
        __syncthreads();
        if (i + 3 < NC) load(i + 3, (i + 3) & 3);

        uint32_t sA = smb + st * STG;
        const uint64_t* Bu = (const uint64_t*)(smc + st * STG + ASZ);
#pragma unroll
        for (int ks = 0; ks < 4; ks++) {
            uint32_t a[4][4], b[8][2];
#pragma unroll
            for (int mt = 0; mt < 4; mt++)
                LDSM4(a[mt][0], a[mt][1], a[mt][2], a[mt][3],
                      sA + arow_off + mt * 16 * AST4 + ks * 32);
            int prow = ks * 4 + lc;
#pragma unroll
            for (int nt = 0; nt < 8; nt++) {
                uint2 v = *(const uint2*)(Bu + (size_t)prow * B_ROWU + wn + nt * 8 + lr);
                b[nt][0] = v.x; b[nt][1] = v.y;
            }
#pragma unroll
            for (int mt = 0; mt < 4; mt++)
#pragma unroll
                for (int nt = 0; nt < 8; nt++)
                    mma16(c[mt][nt], a[mt], b[nt]);
        }
    }

#pragma unroll
    for (int mt = 0; mt < 4; mt++) {
#pragma unroll
        for (int half = 0; half < 2; half++) {
            int r = bm + wm + mt * 16 + lr + half * 8;
            if (r >= cnt) continue;
            if (MODE == 1) {
                uint32_t* row = g_hh + (size_t)(base + r) * (HID / 2);
#pragma unroll
                for (int nt = 0; nt < 8; nt++) {
                    int col = bn + wn + nt * 8 + lc * 2;
                    float v0 = fmaxf(c[mt][nt][half * 2]     + bp[col],     0.f);
                    float v1 = fmaxf(c[mt][nt][half * 2 + 1] + bp[col + 1], 0.f);
                    __half2 hv = __floats2half2_rn(v0, v1);
                    row[col / 2] = *(uint32_t*)&hv;
                }
            } else {
                uint32_t* row = g_yh + (size_t)(base + r) * (DIM / 2);
#pragma unroll
                for (int nt = 0; nt < 8; nt++) {
                    int col = bn + wn + nt * 8 + lc * 2;
                    float v0 = c[mt][nt][half * 2]     + bp[col];
                    float v1 = c[mt][nt][half * 2 + 1] + bp[col + 1];
                    __half2 hv = __floats2half2_rn(v0, v1);
                    row[col / 2] = *(uint32_t*)&hv;
                }
            }
        }
    }
}

// ---------------- launch ---------------------------------------------------------
extern "C" void kernel_launch(void* const* d_in, const int* in_sizes, int n_in,
                              void* d_out, int out_size) {
    const float* x    = (const float*)d_in[0];
    const float* ln_g = (const float*)d_in[1];
    const float* ln_b = (const float*)d_in[2];
    const float* r_w1 = (const float*)d_in[3];
    const float* r_b1 = (const float*)d_in[4];
    const float* r_w2 = (const float*)d_in[5];
    const float* r_b2 = (const float*)d_in[6];
    const float* e_w1 = (const float*)d_in[7];
    const float* e_b1 = (const float*)d_in[8];
    const float* e_w2 = (const float*)d_in[9];
    const float* e_b2 = (const float*)d_in[10];
    float* out = (float*)d_out;

    const int SMEM_R = 4 * (2 * (BM * 80) + 2 * (8 * B_ROWB));    // 215040
    const int SMEM_H = 4 * (BM * 144 + 16 * B_ROWB);              // 206848

    static cudaStream_t s1 = nullptr;
    static cudaEvent_t evFork = nullptr, evJoin = nullptr;
    static int configured = 0;
    if (!configured) {
        cudaFuncSetAttribute(gemm_router16, cudaFuncAttributeMaxDynamicSharedMemorySize, SMEM_R);
        cudaFuncSetAttribute(moe_mma16<1>, cudaFuncAttributeMaxDynamicSharedMemorySize, SMEM_H);
        cudaFuncSetAttribute(moe_mma16<2>, cudaFuncAttributeMaxDynamicSharedMemorySize, SMEM_H);
        cudaStreamCreateWithFlags(&s1, cudaStreamNonBlocking);
        cudaEventCreateWithFlags(&evFork, cudaEventDisableTiming);
        cudaEventCreateWithFlags(&evJoin, cudaEventDisableTiming);
        configured = 1;
    }

    uint64_t *w1hp, *w1lp, *ew1p, *ew2p;
    cudaGetSymbolAddress((void**)&w1hp, g_w1hp);
    cudaGetSymbolAddress((void**)&w1lp, g_w1lp);
    cudaGetSymbolAddress((void**)&ew1p, g_ew1p);
    cudaGetSymbolAddress((void**)&ew2p, g_ew2p);

    // ---- main stream: router prerequisites ----
    zero_cnt_kernel<<<1, 32>>>();
    ln_kernel<<<N_TOK, 256>>>(x, ln_g, ln_b);
    packw2_split<<<(int)(((size_t)DIM * HHALF / 8) / 256), 256>>>(r_w1, w1hp, w1lp, HHALF);

    // ---- fork: expert weight packs overlap with router path ----
    cudaEventRecord(evFork, 0);
    cudaStreamWaitEvent(s1, evFork, 0);
    packw2<<<(int)(((size_t)NEXP * DIM * HID / 8) / 256), 256, 0, s1>>>(e_w1, ew1p, HID);
    packw2<<<(int)(((size_t)NEXP * HID * DIM / 8) / 256), 256, 0, s1>>>(e_w2, ew2p, DIM);
    cudaEventRecord(evJoin, s1);

    // ---- main stream: router path ----
    gemm_router16<<<dim3(HHALF / BN, N_TOK / BM), 256, SMEM_R>>>(w1hp, w1lp, r_b1);
    router_kernel<<<N_TOK / 8, 256>>>(r_w2, r_b2);
    scan_kernel<<<1, 32>>>();
    place_kernel<<<N_TOK / 256, 256>>>();

    // ---- join: expert packs must be done before expert GEMMs ----
    cudaStreamWaitEvent(0, evJoin, 0);

    // expert path
    moe_mma16<1><<<dim3(HID / BN, N_TOK / BM, NEXP), 256, SMEM_H>>>(ew1p, e_b1);
    moe_mma16<2><<<dim3(DIM / BN, N_TOK / BM, NEXP), 256, SMEM_H>>>(ew2p, e_b2);

    // out = x + g1*y1 + g2*y2
    combine_kernel<<<N_TOK, 256>>>(x, out);
}

// round 17
// speedup vs baseline: 1.0012x; 1.0012x over previous
#include <cuda_runtime.h>
#include <cuda_fp16.h>
#include <cstdint>

// Problem constants
#define N_TOK 16384
#define DIM   1024
#define HID   4096
#define HHALF 2048
#define NEXP  8
#define EPSLN 1e-5f

// CTA tile
#define BM 128
#define BN 256
#define B_ROWB 2080    // B smem row stride bytes (256 u64 + 32B pad): conflict-free LDS.64
#define B_ROWU 260     // same in u64

// ---------------- scratch -------------------------------------------------------
__device__ __half    g_xnh[(size_t)N_TOK * DIM];
__device__ __half    g_xnl[(size_t)N_TOK * DIM];
__device__ float     g_hr [(size_t)N_TOK * HHALF];
__device__ uint32_t  g_hh [(size_t)(2 * N_TOK) * (HID / 2)];
__device__ uint32_t  g_yh [(size_t)(2 * N_TOK) * (DIM / 2)];
__device__ uint64_t  g_w1hp[(size_t)(DIM / 4) * HHALF];
__device__ uint64_t  g_w1lp[(size_t)(DIM / 4) * HHALF];
__device__ uint64_t  g_ew1p[(size_t)NEXP * (DIM / 4) * HID];
__device__ uint64_t  g_ew2p[(size_t)NEXP * (HID / 4) * DIM];
__device__ int   g_cnt[NEXP];
__device__ int   g_off[NEXP];
__device__ int   g_fill[NEXP];
__device__ int   g_e12[N_TOK];
__device__ float g_g1[N_TOK];
__device__ float g_g2[N_TOK];
__device__ int   g_list[2 * N_TOK];
__device__ int   g_s1[N_TOK];
__device__ int   g_s2[N_TOK];

// ---------------- helpers -------------------------------------------------------
__device__ __forceinline__ uint32_t smem_u32(const void* p) {
    uint32_t a;
    asm("{ .reg .u64 t; cvta.to.shared.u64 t, %1; cvt.u32.u64 %0, t; }" : "=r"(a) : "l"(p));
    return a;
}
#define CP16(dst, src) \
    asm volatile("cp.async.cg.shared.global [%0], [%1], 16;" :: "r"(dst), "l"(src) : "memory")
#define CP_COMMIT() asm volatile("cp.async.commit_group;" ::: "memory")
#define CP_WAIT2()  asm volatile("cp.async.wait_group 2;" ::: "memory")
#define CP_WAIT0()  asm volatile("cp.async.wait_group 0;" ::: "memory")

#define LDSM4(r0, r1, r2, r3, addr) \
    asm volatile("ldmatrix.sync.aligned.m8n8.x4.shared.b16 {%0,%1,%2,%3}, [%4];" \
                 : "=r"(r0), "=r"(r1), "=r"(r2), "=r"(r3) : "r"(addr))

__device__ __forceinline__ void mma16(float c[4], const uint32_t a[4], const uint32_t b[2]) {
    asm volatile(
        "mma.sync.aligned.m16n8k16.row.col.f32.f16.f16.f32 "
        "{%0,%1,%2,%3}, {%4,%5,%6,%7}, {%8,%9}, {%0,%1,%2,%3};"
        : "+f"(c[0]), "+f"(c[1]), "+f"(c[2]), "+f"(c[3])
        : "r"(a[0]), "r"(a[1]), "r"(a[2]), "r"(a[3]), "r"(b[0]), "r"(b[1]));
}

// ---------------- LayerNorm: fp16 hi + fp16 lo residual --------------------------
__global__ void ln_kernel(const float* __restrict__ x,
                          const float* __restrict__ gam,
                          const float* __restrict__ bet) {
    int row = blockIdx.x;
    const float* xr = x + (size_t)row * DIM;
    float s = 0.f, ss = 0.f;
    for (int i = threadIdx.x; i < DIM; i += 256) {
        float v = xr[i];
        s += v; ss += v * v;
    }
    __shared__ float sh[64];
    for (int o = 16; o; o >>= 1) {
        s  += __shfl_xor_sync(0xFFFFFFFFu, s,  o);
        ss += __shfl_xor_sync(0xFFFFFFFFu, ss, o);
    }
    int w = threadIdx.x >> 5, l = threadIdx.x & 31;
    if (l == 0) { sh[w] = s; sh[w + 32] = ss; }
    __syncthreads();
    if (w == 0) {
        s  = (l < 8) ? sh[l] : 0.f;
        ss = (l < 8) ? sh[l + 32] : 0.f;
        for (int o = 4; o; o >>= 1) {
            s  += __shfl_xor_sync(0xFFFFFFFFu, s,  o);
            ss += __shfl_xor_sync(0xFFFFFFFFu, ss, o);
        }
        if (l == 0) { sh[0] = s; sh[1] = ss; }
    }
    __syncthreads();
    float mu  = sh[0] * (1.0f / DIM);
    float var = sh[1] * (1.0f / DIM) - mu * mu;
    float r   = rsqrtf(var + EPSLN);
    for (int i = threadIdx.x; i < DIM; i += 256) {
        float v = (xr[i] - mu) * r * gam[i] + bet[i];
        __half h = __float2half_rn(v);
        g_xnh[(size_t)row * DIM + i] = h;
        g_xnl[(size_t)row * DIM + i] = __float2half_rn(v - __half2float(h));
    }
}

// ---------------- weight prep: u64-interleaved fp16 pack -------------------------
__global__ void packw2(const float* __restrict__ in, uint64_t* __restrict__ out,
                       int N) {
    size_t idx = (size_t)blockIdx.x * 256 + threadIdx.x;
    size_t nh = (size_t)N / 2;
    size_t rowp = idx / nh;
    size_t n = (idx % nh) * 2;
    size_t ko = rowp >> 2, lc = rowp & 3;
    size_t k0 = ko * 16 + lc * 2;
    const float* w0 = in + k0 * N + n;
    float a0 = w0[0],         a0b = w0[1];
    float a1 = w0[N],         a1b = w0[N + 1];
    float a8 = w0[8 * N],     a8b = w0[8 * N + 1];
    float a9 = w0[9 * N],     a9b = w0[9 * N + 1];
    __half2 h0 = __floats2half2_rn(a0, a1);
    __half2 h1 = __floats2half2_rn(a8, a9);
    __half2 h2 = __floats2half2_rn(a0b, a1b);
    __half2 h3 = __floats2half2_rn(a8b, a9b);
    uint4 o;
    o.x = *(uint32_t*)&h0; o.y = *(uint32_t*)&h1;
    o.z = *(uint32_t*)&h2; o.w = *(uint32_t*)&h3;
    *(uint4*)(out + rowp * N + n) = o;
}

__global__ void packw2_split(const float* __restrict__ in,
                             uint64_t* __restrict__ hi, uint64_t* __restrict__ lo,
                             int N) {
    size_t idx = (size_t)blockIdx.x * 256 + threadIdx.x;
    size_t nh = (size_t)N / 2;
    size_t rowp = idx / nh;
    size_t n = (idx % nh) * 2;
    size_t ko = rowp >> 2, lc = rowp & 3;
    size_t k0 = ko * 16 + lc * 2;
    const float* w0 = in + k0 * N + n;
    float v[8] = { w0[0], w0[N], w0[8 * N], w0[9 * N],
                   w0[1], w0[N + 1], w0[8 * N + 1], w0[9 * N + 1] };
    __half hh[8];
    __half ll[8];
#pragma unroll
    for (int j = 0; j < 8; j++) {
        hh[j] = __float2half_rn(v[j]);
        ll[j] = __float2half_rn(v[j] - __half2float(hh[j]));
    }
    uint4 oh, ol;
    __half2 t;
    t = __halves2half2(hh[0], hh[1]); oh.x = *(uint32_t*)&t;
    t = __halves2half2(hh[2], hh[3]); oh.y = *(uint32_t*)&t;
    t = __halves2half2(hh[4], hh[5]); oh.z = *(uint32_t*)&t;
    t = __halves2half2(hh[6], hh[7]); oh.w = *(uint32_t*)&t;
    t = __halves2half2(ll[0], ll[1]); ol.x = *(uint32_t*)&t;
    t = __halves2half2(ll[2], ll[3]); ol.y = *(uint32_t*)&t;
    t = __halves2half2(ll[4], ll[5]); ol.z = *(uint32_t*)&t;
    t = __halves2half2(ll[6], ll[7]); ol.w = *(uint32_t*)&t;
    *(uint4*)(hi + rowp * N + n) = oh;
    *(uint4*)(lo + rowp * N + n) = ol;
}

// ---------------- Router logits + softmax top-2 + gates (float4 MLP) -------------
__global__ void router_kernel(const float* __restrict__ w2,
                              const float* __restrict__ b2) {
    int warp = threadIdx.x >> 5, lane = threadIdx.x & 31;
    int t = blockIdx.x * 8 + warp;
    const float4* hrow = (const float4*)(g_hr + (size_t)t * HHALF);
    float acc[NEXP] = {};
#pragma unroll 4
    for (int i = lane; i < HHALF / 4; i += 32) {
        float4 h4 = hrow[i];
        const float4* wp = (const float4*)(w2 + (size_t)i * 4 * NEXP);
        float hv[4] = {h4.x, h4.y, h4.z, h4.w};
#pragma unroll
        for (int j = 0; j < 4; j++) {
            float4 w0 = __ldg(wp + j * 2), w1 = __ldg(wp + j * 2 + 1);
            acc[0] += hv[j] * w0.x; acc[1] += hv[j] * w0.y;
            acc[2] += hv[j] * w0.z; acc[3] += hv[j] * w0.w;
            acc[4] += hv[j] * w1.x; acc[5] += hv[j] * w1.y;
            acc[6] += hv[j] * w1.z; acc[7] += hv[j] * w1.w;
        }
    }
    for (int o = 16; o; o >>= 1)
#pragma unroll
        for (int e = 0; e < NEXP; e++)
            acc[e] += __shfl_xor_sync(0xFFFFFFFFu, acc[e], o);
    if (lane == 0) {
        float l[NEXP];
#pragma unroll
        for (int e = 0; e < NEXP; e++) l[e] = acc[e] + b2[e];
        int e1 = 0;
        for (int e = 1; e < NEXP; e++) if (l[e] > l[e1]) e1 = e;
        int e2 = -1;
        for (int e = 0; e < NEXP; e++) {
            if (e == e1) continue;
            if (e2 < 0 || l[e] > l[e2]) e2 = e;
        }
        float ed  = expf(l[e2] - l[e1]);
        float inv = 1.f / (1.f + ed);
        g_e12[t] = e1 | (e2 << 8);
        g_g1[t] = inv;
        g_g2[t] = ed * inv;
        atomicAdd(&g_cnt[e1], 1);
        atomicAdd(&g_cnt[e2], 1);
    }
}

__global__ void zero_cnt_kernel() {
    if (threadIdx.x < NEXP) g_cnt[threadIdx.x] = 0;
}
__global__ void scan_kernel() {
    if (threadIdx.x == 0) {
        int s = 0;
        for (int e = 0; e < NEXP; e++) { g_off[e] = s; s += g_cnt[e]; g_fill[e] = 0; }
    }
}
__global__ void place_kernel() {
    int t = blockIdx.x * 256 + threadIdx.x;
    if (t >= N_TOK) return;
    int e12 = g_e12[t];
    int e1 = e12 & 0xFF, e2 = e12 >> 8;
    int s1 = g_off[e1] + atomicAdd(&g_fill[e1], 1);
    g_list[s1] = t; g_s1[t] = s1;
    int s2 = g_off[e2] + atomicAdd(&g_fill[e2], 1);
    g_list[s2] = t; g_s2[t] = s2;
}

// ---------------- final combine: out = x + g1*y[s1] + g2*y[s2] (y fp16) ----------
__global__ void combine_kernel(const float* __restrict__ x, float* __restrict__ out) {
    int t = blockIdx.x;
    int s1 = g_s1[t], s2 = g_s2[t];
    float a = g_g1[t], b = g_g2[t];
    int i = threadIdx.x;
    float4 xv = ((const float4*)(x + (size_t)t * DIM))[i];
    uint2 u1 = ((const uint2*)(g_yh + (size_t)s1 * (DIM / 2)))[i];
    uint2 u2 = ((const uint2*)(g_yh + (size_t)s2 * (DIM / 2)))[i];
    float2 p1a = __half22float2(*(__half2*)&u1.x);
    float2 p1b = __half22float2(*(__half2*)&u1.y);
    float2 p2a = __half22float2(*(__half2*)&u2.x);
    float2 p2b = __half22float2(*(__half2*)&u2.y);
    float4 r;
    r.x = xv.x + a * p1a.x + b * p2a.x;
    r.y = xv.y + a * p1a.y + b * p2a.y;
    r.z = xv.z + a * p1b.x + b * p2b.x;
    r.w = xv.w + a * p1b.y + b * p2b.y;
    ((float4*)(out + (size_t)t * DIM))[i] = r;
}

// ---------------- Router GEMM: split-fp16, ldmatrix + LDS.64, 4-stage ------------
__global__ void __launch_bounds__(256, 1)
gemm_router16(const uint64_t* __restrict__ Wh, const uint64_t* __restrict__ Wl,
              const float* __restrict__ bias) {
    constexpr int NC   = DIM / 32;
    constexpr int AST4 = 80;
    constexpr int ASZ  = BM * AST4;
    constexpr int BSZ  = 8 * B_ROWB;
    constexpr int STG  = 2 * ASZ + 2 * BSZ;

    int bm = blockIdx.y * BM, bn = blockIdx.x * BN;
    extern __shared__ char smc[];
    uint32_t smb = smem_u32(smc);
    int tid = threadIdx.x, lane = tid & 31, wid = tid >> 5;
    int wm = (wid >> 2) * 64, wn = (wid & 3) * 64;

    const uint32_t* ah[2];
    const uint32_t* al[2];
    uint32_t adst[2];
#pragma unroll
    for (int j = 0; j < 2; j++) {
        int id = tid + 256 * j;
        int row = id >> 2, c4 = id & 3;
        adst[j] = (uint32_t)row * AST4 + c4 * 16;
        ah[j] = (const uint32_t*)g_xnh + (size_t)(bm + row) * (DIM / 2) + c4 * 4;
        al[j] = (const uint32_t*)g_xnl + (size_t)(bm + row) * (DIM / 2) + c4 * 4;
    }
    const uint64_t* bh[4];
    const uint64_t* bl[4];
    uint32_t bdst[4];
#pragma unroll
    for (int j = 0; j < 4; j++) {
        int id = tid + 256 * j;
        int p = id >> 7, nn = (id & 127) * 2;
        bdst[j] = (uint32_t)p * B_ROWB + nn * 8;
        bh[j] = Wh + (size_t)p * HHALF + bn + nn;
        bl[j] = Wl + (size_t)p * HHALF + bn + nn;
    }

    auto load = [&](int i, int st) {
        uint32_t s0 = smb + (uint32_t)st * STG;
        int ko = i * 16;
        size_t bko = (size_t)i * 8 * HHALF;
#pragma unroll
        for (int j = 0; j < 2; j++) {
            CP16(s0 + adst[j], ah[j] + ko);
            CP16(s0 + ASZ + adst[j], al[j] + ko);
        }
#pragma unroll
        for (int j = 0; j < 4; j++) {
            CP16(s0 + 2 * ASZ + bdst[j], bh[j] + bko);
            CP16(s0 + 2 * ASZ + BSZ + bdst[j], bl[j] + bko);
        }
        CP_COMMIT();
    };

    float c[4][8][4] = {};
    load(0, 0);
    load(1, 1);
    load(2, 2);

    int lr = lane >> 2, lc = lane & 3;
    uint32_t arow_off = (uint32_t)(wm + (lane & 15)) * AST4 + (lane >> 4) * 16;
    for (int i = 0; i < NC; i++) {
        int st = i & 3;
        if (i + 3 < NC) { CP_WAIT2(); } else { CP_WAIT0(); }
        __syncthreads();
        if (i + 3 < NC) load(i + 3, (i + 3) & 3);

        uint32_t sA  = smb + st * STG;
        uint32_t sA2 = sA + ASZ;
        const uint64_t* Bu = (const uint64_t*)(smc + st * STG + 2 * ASZ);
        const uint64_t* Bl2 = (const uint64_t*)(smc + st * STG + 2 * ASZ + BSZ);
#pragma unroll
        for (int ks = 0; ks < 2; ks++) {
            uint32_t a[4][4], a2[4][4], b[8][2], b2[8][2];
#pragma unroll
            for (int mt = 0; mt < 4; mt++) {
                LDSM4(a[mt][0], a[mt][1], a[mt][2], a[mt][3],
                      sA + arow_off + mt * 16 * AST4 + ks * 32);
                LDSM4(a2[mt][0], a2[mt][1], a2[mt][2], a2[mt][3],
                      sA2 + arow_off + mt * 16 * AST4 + ks * 32);
            }
            int prow = ks * 4 + lc;
#pragma unroll
            for (int nt = 0; nt < 8; nt++) {
                uint2 v  = *(const uint2*)(Bu  + (size_t)prow * B_ROWU + wn + nt * 8 + lr);
                uint2 v2 = *(const uint2*)(Bl2 + (size_t)prow * B_ROWU + wn + nt * 8 + lr);
                b[nt][0] = v.x;  b[nt][1] = v.y;
                b2[nt][0] = v2.x; b2[nt][1] = v2.y;
            }
#pragma unroll
            for (int mt = 0; mt < 4; mt++)
#pragma unroll
                for (int nt = 0; nt < 8; nt++) {
                    mma16(c[mt][nt], a[mt],  b[nt]);
                    mma16(c[mt][nt], a[mt],  b2[nt]);
                    mma16(c[mt][nt], a2[mt], b[nt]);
                }
        }
    }

#pragma unroll
    for (int mt = 0; mt < 4; mt++) {
#pragma unroll
        for (int half = 0; half < 2; half++) {
            int r = bm + wm + mt * 16 + lr + half * 8;
            float* row = g_hr + (size_t)r * HHALF;
#pragma unroll
            for (int nt = 0; nt < 8; nt++) {
                int col = bn + wn + nt * 8 + lc * 2;
                float v0 = c[mt][nt][half * 2]     + bias[col];
                float v1 = c[mt][nt][half * 2 + 1] + bias[col + 1];
                float2 st2;
                st2.x = fmaxf(v0, 0.f); st2.y = fmaxf(v1, 0.f);
                *(float2*)(row + col) = st2;
            }
        }
    }
}

// ---------------- Expert GEMMs: fp16, ldmatrix + LDS.64, BKC=64, 4-stage ---------
template <int MODE>
__global__ void __launch_bounds__(256, 1)
moe_mma16(const uint64_t* __restrict__ Wp, const float* __restrict__ bias) {
    constexpr int Kd   = (MODE == 2) ? HID : DIM;
    constexpr int Nd   = (MODE == 1) ? HID : DIM;
    constexpr int NC   = Kd / 64;
    constexpr int AST4 = 144;
    constexpr int ASZ  = BM * AST4;
    constexpr int BSZ  = 16 * B_ROWB;
    constexpr int STG  = ASZ + BSZ;

    int bm = blockIdx.y * BM, bn = blockIdx.x * BN;
    int e = blockIdx.z;
    int cnt = g_cnt[e];
    if (bm >= cnt) return;
    int base = g_off[e];
    const uint64_t* W = Wp + (size_t)e * (Kd / 4) * Nd;
    const float* bp = bias + e * Nd;

    extern __shared__ char smc[];
    uint32_t smb = smem_u32(smc);
    int tid = threadIdx.x, lane = tid & 31, wid = tid >> 5;
    int wm = (wid >> 2) * 64, wn = (wid & 3) * 64;

    const uint32_t* ah[4];
    uint32_t adst[4];
#pragma unroll
    for (int j = 0; j < 4; j++) {
        int id = tid + 256 * j;
        int row = id >> 3, c4 = id & 7;
        adst[j] = (uint32_t)row * AST4 + c4 * 16;
        int r = bm + row; if (r >= cnt) r = cnt - 1;
        if (MODE == 1) {
            int tok = g_list[base + r];
            ah[j] = (const uint32_t*)g_xnh + (size_t)tok * (DIM / 2) + c4 * 4;
        } else {
            ah[j] = g_hh + (size_t)(base + r) * (HID / 2) + c4 * 4;
        }
    }
    const uint64_t* bh[8];
    uint32_t bdst[8];
#pragma unroll
    for (int j = 0; j < 8; j++) {
        int id = tid + 256 * j;
        int p = id >> 7, nn = (id & 127) * 2;
        bdst[j] = (uint32_t)p * B_ROWB + nn * 8;
        bh[j] = W + (size_t)p * Nd + bn + nn;
    }

    auto load = [&](int i, int st) {
        uint32_t s0 = smb + (uint32_t)st * STG;
        int ko = i * 32;
        size_t bko = (size_t)i * 16 * Nd;
#pragma unroll
        for (int j = 0; j < 4; j++) CP16(s0 + adst[j], ah[j] + ko);
#pragma unroll
        for (int j = 0; j < 8; j++) CP16(s0 + ASZ + bdst[j], bh[j] + bko);
        CP_COMMIT();
    };

    float c[4][8][4] = {};
    load(0, 0);
    load(1, 1);
    load(2, 2);

    int lr = lane >> 2, lc = lane & 3;
    uint32_t arow_off = (uint32_t)(wm + (lane & 15)) * AST4 + (lane >> 4) * 16;
    for (int i = 0; i < NC; i++) {
        int st = i & 3;
        if (i + 3 < NC) { CP_WAIT2(); } else { CP_WAIT0(); }
        __syncthreads();
        if (i + 3 < NC) load(i + 3, (i + 3) & 3);

        uint32_t sA = smb + st * STG;
        const uint64_t* Bu = (const uint64_t*)(smc + st * STG + ASZ);
#pragma unroll
        for (int ks = 0; ks < 4; ks++) {
            uint32_t a[4][4], b[8][2];
#pragma unroll
            for (int mt = 0; mt < 4; mt++)
                LDSM4(a[mt][0], a[mt][1], a[mt][2], a[mt][3],
                      sA + arow_off + mt * 16 * AST4 + ks * 32);
            int prow = ks * 4 + lc;
#pragma unroll
            for (int nt = 0; nt < 8; nt++) {
                uint2 v = *(const uint2*)(Bu + (size_t)prow * B_ROWU + wn + nt * 8 + lr);
                b[nt][0] = v.x; b[nt][1] = v.y;
            }
#pragma unroll
            for (int mt = 0; mt < 4; mt++)
#pragma unroll
                for (int nt = 0; nt < 8; nt++)
                    mma16(c[mt][nt], a[mt], b[nt]);
        }
    }

#pragma unroll
    for (int mt = 0; mt < 4; mt++) {
#pragma unroll
        for (int half = 0; half < 2; half++) {
            int r = bm + wm + mt * 16 + lr + half * 8;
            if (r >= cnt) continue;
            if (MODE == 1) {
                uint32_t* row = g_hh + (size_t)(base + r) * (HID / 2);
#pragma unroll
                for (int nt = 0; nt < 8; nt++) {
                    int col = bn + wn + nt * 8 + lc * 2;
                    float v0 = fmaxf(c[mt][nt][half * 2]     + bp[col],     0.f);
                    float v1 = fmaxf(c[mt][nt][half * 2 + 1] + bp[col + 1], 0.f);
                    __half2 hv = __floats2half2_rn(v0, v1);
                    row[col / 2] = *(uint32_t*)&hv;
                }
            } else {
                uint32_t* row = g_yh + (size_t)(base + r) * (DIM / 2);
#pragma unroll
                for (int nt = 0; nt < 8; nt++) {
                    int col = bn + wn + nt * 8 + lc * 2;
                    float v0 = c[mt][nt][half * 2]     + bp[col];
                    float v1 = c[mt][nt][half * 2 + 1] + bp[col + 1];
                    __half2 hv = __floats2half2_rn(v0, v1);
                    row[col / 2] = *(uint32_t*)&hv;
                }
            }
        }
    }
}

// ---------------- launch ---------------------------------------------------------
extern "C" void kernel_launch(void* const* d_in, const int* in_sizes, int n_in,
                              void* d_out, int out_size) {
    const float* x    = (const float*)d_in[0];
    const float* ln_g = (const float*)d_in[1];
    const float* ln_b = (const float*)d_in[2];
    const float* r_w1 = (const float*)d_in[3];
    const float* r_b1 = (const float*)d_in[4];
    const float* r_w2 = (const float*)d_in[5];
    const float* r_b2 = (const float*)d_in[6];
    const float* e_w1 = (const float*)d_in[7];
    const float* e_b1 = (const float*)d_in[8];
    const float* e_w2 = (const float*)d_in[9];
    const float* e_b2 = (const float*)d_in[10];
    float* out = (float*)d_out;

    const int SMEM_R = 4 * (2 * (BM * 80) + 2 * (8 * B_ROWB));    // 215040
    const int SMEM_H = 4 * (BM * 144 + 16 * B_ROWB);              // 206848

    static int configured = 0;
    if (!configured) {
        cudaFuncSetAttribute(gemm_router16, cudaFuncAttributeMaxDynamicSharedMemorySize, SMEM_R);
        cudaFuncSetAttribute(moe_mma16<1>, cudaFuncAttributeMaxDynamicSharedMemorySize, SMEM_H);
        cudaFuncSetAttribute(moe_mma16<2>, cudaFuncAttributeMaxDynamicSharedMemorySize, SMEM_H);
        configured = 1;
    }

    uint64_t *w1hp, *w1lp, *ew1p, *ew2p;
    cudaGetSymbolAddress((void**)&w1hp, g_w1hp);
    cudaGetSymbolAddress((void**)&w1lp, g_w1lp);
    cudaGetSymbolAddress((void**)&ew1p, g_ew1p);
    cudaGetSymbolAddress((void**)&ew2p, g_ew2p);

    // serial launch order (R15 topology — proven fastest)
    zero_cnt_kernel<<<1, 32>>>();
    ln_kernel<<<N_TOK, 256>>>(x, ln_g, ln_b);
    packw2_split<<<(int)(((size_t)DIM * HHALF / 8) / 256), 256>>>(r_w1, w1hp, w1lp, HHALF);
    packw2<<<(int)(((size_t)NEXP * DIM * HID / 8) / 256), 256>>>(e_w1, ew1p, HID);
    packw2<<<(int)(((size_t)NEXP * HID * DIM / 8) / 256), 256>>>(e_w2, ew2p, DIM);

    // router path
    gemm_router16<<<dim3(HHALF / BN, N_TOK / BM), 256, SMEM_R>>>(w1hp, w1lp, r_b1);
    router_kernel<<<N_TOK / 8, 256>>>(r_w2, r_b2);
    scan_kernel<<<1, 32>>>();
    place_kernel<<<N_TOK / 256, 256>>>();

    // expert path
    moe_mma16<1><<<dim3(HID / BN, N_TOK / BM, NEXP), 256, SMEM_H>>>(ew1p, e_b1);
    moe_mma16<2><<<dim3(DIM / BN, N_TOK / BM, NEXP), 256, SMEM_H>>>(ew2p, e_b2);

    // out = x + g1*y1 + g2*y2
    combine_kernel<<<N_TOK, 256>>>(x, out);
}